// round 10
// baseline (speedup 1.0000x reference)
#include <cuda_runtime.h>
#include <cstdint>

// SwappingCorruption: out[i,j] = mask[i,j] ? x[i, perm[i,j]] : x[i,j]
// B=16384 rows, F=2048 cols, fp32; mask/perm int32.
//
// R9 post-mortem: DRAM-bound, ~508 MB observed both with and without SMEM
// staging. perm contributes ~124 MB — consistent with either (a) 128B-line
// DRAM fill granularity, or (b) the guarded int4 perm load being speculated
// into an unconditional load. This round pins down (b): the perm load is an
// explicitly predicated inline-PTX ld.global.nc.v4 that provably issues no
// memory request when the 4-wide mask quad is all zero (p = 0.9^4 = 0.656).
// Gathers are served from SMEM (row staged once; barrier measured free in
// R8/R9), so gather traffic is deterministically DRAM-free.

static constexpr int N_FEAT  = 2048;
static constexpr int THREADS = 256;
static constexpr int VEC_PER_THREAD = (N_FEAT / 4) / THREADS;  // 2

__global__ __launch_bounds__(THREADS)
void swap_corruption_kernel(const float* __restrict__ x,
                            const int*   __restrict__ mask,
                            const int*   __restrict__ perm,
                            float* __restrict__ out)
{
    __shared__ float row[N_FEAT];

    const size_t base = (size_t)blockIdx.x * N_FEAT;
    const float4* xr  = reinterpret_cast<const float4*>(x + base);
    const int4*   mr  = reinterpret_cast<const int4*>(mask + base);
    const int4*   pr  = reinterpret_cast<const int4*>(perm + base);
    float4*       owr = reinterpret_cast<float4*>(out + base);
    float4* srow4 = reinterpret_cast<float4*>(row);

    const int t = threadIdx.x;

    // Stage the row into SMEM (coalesced float4) and pre-load mask quads.
    float4 v[VEC_PER_THREAD];
    int4   m[VEC_PER_THREAD];
    #pragma unroll
    for (int i = 0; i < VEC_PER_THREAD; ++i) {
        const int idx = t + i * THREADS;
        v[i] = xr[idx];
        m[i] = __ldg(&mr[idx]);
        srow4[idx] = v[i];
    }
    __syncthreads();

    #pragma unroll
    for (int i = 0; i < VEC_PER_THREAD; ++i) {
        const int idx = t + i * THREADS;
        const int any = m[i].x | m[i].y | m[i].z | m[i].w;
        if (any) {
            // Explicitly predicated v4 load: guaranteed no speculative issue,
            // no memory request when the quad is all-unmasked.
            int px, py, pz, pw;
            asm volatile(
                "{\n\t"
                ".reg .pred q;\n\t"
                "setp.ne.s32 q, %4, 0;\n\t"
                "@q ld.global.nc.v4.s32 {%0, %1, %2, %3}, [%5];\n\t"
                "}"
                : "=r"(px), "=r"(py), "=r"(pz), "=r"(pw)
                : "r"(any), "l"(pr + idx)
                : "memory");
            if (m[i].x) v[i].x = row[px];
            if (m[i].y) v[i].y = row[py];
            if (m[i].z) v[i].z = row[pz];
            if (m[i].w) v[i].w = row[pw];
        }
        owr[idx] = v[i];
    }
}

extern "C" void kernel_launch(void* const* d_in, const int* in_sizes, int n_in,
                              void* d_out, int out_size)
{
    // metadata order: x (float32), swap_mask (int32 0/1), perm (int32)
    const float* x    = (const float*)d_in[0];
    const int*   mask = (const int*)d_in[1];
    const int*   perm = (const int*)d_in[2];
    float*       out  = (float*)d_out;

    const int batch = in_sizes[0] / N_FEAT;  // 16384
    swap_corruption_kernel<<<batch, THREADS>>>(x, mask, perm, out);
}

// round 11
// speedup vs baseline: 1.0037x; 1.0037x over previous
#include <cuda_runtime.h>
#include <cstdint>

// SwappingCorruption: out[i,j] = mask[i,j] ? x[i, perm[i,j]] : x[i,j]
// B=16384 rows, F=2048 cols, fp32; mask/perm int32.
//
// R10 conclusion: DRAM fill granularity makes conditional perm skipping
// worthless (~97% of 128B lines touched at p=0.1 mask). Byte floor ~508 MB.
// This round maximizes DRAM stream efficiency instead: all four tensors are
// read/written as perfectly dense coalesced 128-bit streams (no conditional
// scatter on perm), the epilogue is branchless selects, and all 6 LDG.128
// per thread are front-batched ahead of the single barrier (MLP_p1=6).
// Gathers are unconditional LDS from the SMEM-staged row (L1 has headroom).

static constexpr int N_FEAT  = 2048;
static constexpr int THREADS = 256;
static constexpr int VEC_PER_THREAD = (N_FEAT / 4) / THREADS;  // 2

__global__ __launch_bounds__(THREADS)
void swap_corruption_kernel(const float* __restrict__ x,
                            const int*   __restrict__ mask,
                            const int*   __restrict__ perm,
                            float* __restrict__ out)
{
    __shared__ float row[N_FEAT];

    const size_t base = (size_t)blockIdx.x * N_FEAT;
    const float4* xr  = reinterpret_cast<const float4*>(x + base);
    const int4*   mr  = reinterpret_cast<const int4*>(mask + base);
    const int4*   pr  = reinterpret_cast<const int4*>(perm + base);
    float4*       owr = reinterpret_cast<float4*>(out + base);
    float4* srow4 = reinterpret_cast<float4*>(row);

    const int t = threadIdx.x;

    // Front-batch ALL global loads: 2x x, 2x mask, 2x perm (6 LDG.128).
    float4 v[VEC_PER_THREAD];
    int4   m[VEC_PER_THREAD];
    int4   p[VEC_PER_THREAD];
    #pragma unroll
    for (int i = 0; i < VEC_PER_THREAD; ++i) {
        const int idx = t + i * THREADS;
        v[i] = xr[idx];
        m[i] = __ldg(&mr[idx]);
        p[i] = __ldg(&pr[idx]);
    }
    #pragma unroll
    for (int i = 0; i < VEC_PER_THREAD; ++i) {
        srow4[t + i * THREADS] = v[i];
    }
    __syncthreads();

    // Branchless: unconditional SMEM gather + select. No divergence, no BSSY.
    #pragma unroll
    for (int i = 0; i < VEC_PER_THREAD; ++i) {
        const int idx = t + i * THREADS;
        float4 r = v[i];
        r.x = m[i].x ? row[p[i].x] : r.x;
        r.y = m[i].y ? row[p[i].y] : r.y;
        r.z = m[i].z ? row[p[i].z] : r.z;
        r.w = m[i].w ? row[p[i].w] : r.w;
        owr[idx] = r;
    }
}

extern "C" void kernel_launch(void* const* d_in, const int* in_sizes, int n_in,
                              void* d_out, int out_size)
{
    // metadata order: x (float32), swap_mask (int32 0/1), perm (int32)
    const float* x    = (const float*)d_in[0];
    const int*   mask = (const int*)d_in[1];
    const int*   perm = (const int*)d_in[2];
    float*       out  = (float*)d_out;

    const int batch = in_sizes[0] / N_FEAT;  // 16384
    swap_corruption_kernel<<<batch, THREADS>>>(x, mask, perm, out);
}